// round 3
// baseline (speedup 1.0000x reference)
#include <cuda_runtime.h>
#include <cstdint>

// Problem constants (fixed shapes from reference)
#define B_   32
#define D_   64
#define H_   64
#define W_   64
#define K_   512
#define HW_  (H_ * W_)               // 4096
#define NPTS (B_ * HW_)              // 131072
#define NELEM ((long long)NPTS * D_) // 8388608
#define TPB  256
#define GRID (NPTS / TPB)            // 512

// Pairwise approx-vs-exact discrepancy bound ~3.5e-5; 3x safety margin.
#define EPS_MARGIN 1.0e-4f

typedef unsigned long long u64;

__device__ double g_loss_accum;

__device__ __forceinline__ u64 ffma2(u64 a, u64 b, u64 c) {
    u64 d;
    asm("fma.rn.f32x2 %0, %1, %2, %3;" : "=l"(d) : "l"(a), "l"(b), "l"(c));
    return d;
}
__device__ __forceinline__ float2 unpack2(u64 v) {
    float lo, hi;
    asm("mov.b64 {%0, %1}, %2;" : "=f"(lo), "=f"(hi) : "l"(v));
    return make_float2(lo, hi);
}
__device__ __forceinline__ u64 pack2(float lo, float hi) {
    u64 r;
    asm("mov.b64 %0, {%1, %2};" : "=l"(r) : "f"(lo), "f"(hi));
    return r;
}

__global__ void vq_zero_kernel() { g_loss_accum = 0.0; }

__global__ __launch_bounds__(TPB, 1)
void vq_main_kernel(const float* __restrict__ z,
                    const float* __restrict__ cb,
                    float* __restrict__ out) {
    // Dynamic smem: codebook [K*D] + ||e||^2 [K] + reduction scratch [32]
    extern __shared__ float smem[];
    float* s_cb  = smem;                 // 512*64 floats = 128 KB
    float* s_y   = smem + K_ * D_;       // 512 floats (sum e_i^2, exact seq order)
    float* s_red = s_y + K_;             // 32 floats

    const int tid = threadIdx.x;

    // Stage codebook into smem
    {
        const float4* g4 = reinterpret_cast<const float4*>(cb);
        float4* s4 = reinterpret_cast<float4*>(s_cb);
        #pragma unroll
        for (int i = tid; i < K_ * D_ / 4; i += TPB) s4[i] = g4[i];
    }
    __syncthreads();

    // y_k = sum_i fl(e_i^2), SEQUENTIAL fp32 adds (XLA reduce order, no fma)
    for (int k = tid; k < K_; k += TPB) {
        const float* e = s_cb + k * D_;
        float s = 0.f;
        #pragma unroll
        for (int c = 0; c < D_; c++) s = __fadd_rn(s, __fmul_rn(e[c], e[c]));
        s_y[k] = s;
    }
    __syncthreads();

    // One point per thread
    const int n  = blockIdx.x * TPB + tid;
    const int b  = n >> 12;          // / 4096
    const int hw = n & (HW_ - 1);
    const float* zp_g = z + (size_t)b * D_ * HW_ + hw;

    // Load feature vector: scalar copy (for exact paths) + packed copy (fast scan)
    float zf[D_];
    #pragma unroll
    for (int i = 0; i < D_; i++) zf[i] = __ldg(zp_g + (size_t)i * HW_);
    u64 zq[D_ / 2];
    #pragma unroll
    for (int i = 0; i < D_ / 2; i++) zq[i] = pack2(zf[2 * i], zf[2 * i + 1]);

    // x = sum_i fl(z_i^2), sequential fp32 (needed by exact fallback)
    float x = 0.f;
    #pragma unroll
    for (int i = 0; i < D_; i++) x = __fadd_rn(x, __fmul_rn(zf[i], zf[i]));

    // ---------- Phase 1: fast approximate scan (packed f32x2) ----------
    // t_k = y_k - 2 * m_k  (m_k via pairwise packed tree). Track min1/min2.
    float min1 = 3.4e38f, min2 = 3.4e38f;
    int   bestk = 0;
    const ulonglong2* cbv = reinterpret_cast<const ulonglong2*>(s_cb);

    for (int k = 0; k < K_; k += 2) {
        const ulonglong2* r0 = cbv + (k + 0) * 16;
        const ulonglong2* r1 = cbv + (k + 1) * 16;
        u64 a0 = 0ull, b0 = 0ull, a1 = 0ull, b1 = 0ull;
        #pragma unroll
        for (int i = 0; i < 16; i += 2) {
            ulonglong2 e0a = r0[i], e0b = r0[i + 1];
            ulonglong2 e1a = r1[i], e1b = r1[i + 1];
            a0 = ffma2(zq[2 * i + 0], e0a.x, a0);
            b0 = ffma2(zq[2 * i + 1], e0a.y, b0);
            a0 = ffma2(zq[2 * i + 2], e0b.x, a0);
            b0 = ffma2(zq[2 * i + 3], e0b.y, b0);
            a1 = ffma2(zq[2 * i + 0], e1a.x, a1);
            b1 = ffma2(zq[2 * i + 1], e1a.y, b1);
            a1 = ffma2(zq[2 * i + 2], e1b.x, a1);
            b1 = ffma2(zq[2 * i + 3], e1b.y, b1);
        }
        float2 fa0 = unpack2(a0), fb0 = unpack2(b0);
        float2 fa1 = unpack2(a1), fb1 = unpack2(b1);
        float t0 = fmaf(-2.f, (fa0.x + fa0.y) + (fb0.x + fb0.y), s_y[k + 0]);
        float t1 = fmaf(-2.f, (fa1.x + fa1.y) + (fb1.x + fb1.y), s_y[k + 1]);
        if (t0 < min1)      { min2 = min1; min1 = t0; bestk = k; }
        else if (t0 < min2) { min2 = t0; }
        if (t1 < min1)      { min2 = min1; min1 = t1; bestk = k + 1; }
        else if (t1 < min2) { min2 = t1; }
    }

    // ---------- Phase 2: exact fallback for near-ties (rare) ----------
    const bool need = (min2 - min1) < EPS_MARGIN;
    if (__any_sync(0xffffffffu, need)) {
        // Bit-exact reference replication: per-code sequential fma chain,
        // d = fl(fl(x+y) - 2m), strict < keeps first index.
        float best = 3.4e38f;
        int   bk   = 0;
        const float4* cb4 = reinterpret_cast<const float4*>(s_cb);
        for (int k = 0; k < K_; k += 4) {
            float a0 = 0.f, a1 = 0.f, a2 = 0.f, a3 = 0.f;
            const float4* r0 = cb4 + (k + 0) * (D_ / 4);
            const float4* r1 = cb4 + (k + 1) * (D_ / 4);
            const float4* r2 = cb4 + (k + 2) * (D_ / 4);
            const float4* r3 = cb4 + (k + 3) * (D_ / 4);
            #pragma unroll
            for (int i = 0; i < D_ / 4; i++) {
                float4 e0 = r0[i], e1 = r1[i], e2 = r2[i], e3 = r3[i];
                a0 = __fmaf_rn(zf[4*i+0], e0.x, a0);
                a1 = __fmaf_rn(zf[4*i+0], e1.x, a1);
                a2 = __fmaf_rn(zf[4*i+0], e2.x, a2);
                a3 = __fmaf_rn(zf[4*i+0], e3.x, a3);
                a0 = __fmaf_rn(zf[4*i+1], e0.y, a0);
                a1 = __fmaf_rn(zf[4*i+1], e1.y, a1);
                a2 = __fmaf_rn(zf[4*i+1], e2.y, a2);
                a3 = __fmaf_rn(zf[4*i+1], e3.y, a3);
                a0 = __fmaf_rn(zf[4*i+2], e0.z, a0);
                a1 = __fmaf_rn(zf[4*i+2], e1.z, a1);
                a2 = __fmaf_rn(zf[4*i+2], e2.z, a2);
                a3 = __fmaf_rn(zf[4*i+2], e3.z, a3);
                a0 = __fmaf_rn(zf[4*i+3], e0.w, a0);
                a1 = __fmaf_rn(zf[4*i+3], e1.w, a1);
                a2 = __fmaf_rn(zf[4*i+3], e2.w, a2);
                a3 = __fmaf_rn(zf[4*i+3], e3.w, a3);
            }
            float d0 = __fadd_rn(__fadd_rn(x, s_y[k + 0]), -__fmul_rn(2.f, a0));
            float d1 = __fadd_rn(__fadd_rn(x, s_y[k + 1]), -__fmul_rn(2.f, a1));
            float d2 = __fadd_rn(__fadd_rn(x, s_y[k + 2]), -__fmul_rn(2.f, a2));
            float d3 = __fadd_rn(__fadd_rn(x, s_y[k + 3]), -__fmul_rn(2.f, a3));
            if (d0 < best) { best = d0; bk = k + 0; }
            if (d1 < best) { best = d1; bk = k + 1; }
            if (d2 < best) { best = d2; bk = k + 2; }
            if (d3 < best) { best = d3; bk = k + 3; }
        }
        if (need) bestk = bk;
    }

    // ---------- Output + loss ----------
    float* op = out + (size_t)b * D_ * HW_ + hw;
    const float* e = s_cb + bestk * D_;
    float lsum = 0.f;
    #pragma unroll
    for (int i = 0; i < D_; i++) {
        float q  = e[i];
        float dd = __fadd_rn(q, -zf[i]);            // fl(q - z)
        lsum = __fmaf_rn(dd, dd, lsum);
        op[(size_t)i * HW_] = __fadd_rn(zf[i], dd); // fl(z + fl(q - z))
    }

    // Block reduction of lsum -> double atomic
    #pragma unroll
    for (int off = 16; off > 0; off >>= 1)
        lsum += __shfl_down_sync(0xffffffffu, lsum, off);
    __syncthreads();
    if ((tid & 31) == 0) s_red[tid >> 5] = lsum;
    __syncthreads();
    if (tid < 32) {
        float v = (tid < TPB / 32) ? s_red[tid] : 0.f;
        #pragma unroll
        for (int off = 16; off > 0; off >>= 1)
            v += __shfl_down_sync(0xffffffffu, v, off);
        if (tid == 0) atomicAdd(&g_loss_accum, (double)v);
    }
}

__global__ void vq_finalize_kernel(float* __restrict__ out, int loss_idx) {
    out[loss_idx] = (float)(g_loss_accum * 1.25 / (double)NELEM);
}

extern "C" void kernel_launch(void* const* d_in, const int* in_sizes, int n_in,
                              void* d_out, int out_size) {
    const float* z  = (const float*)d_in[0];
    const float* cb = (const float*)d_in[1];
    float* out = (float*)d_out;

    const int smem_bytes = (K_ * D_ + K_ + 32) * sizeof(float); // 133248 B
    static bool attr_set = false;
    if (!attr_set) {
        cudaFuncSetAttribute(vq_main_kernel,
                             cudaFuncAttributeMaxDynamicSharedMemorySize,
                             smem_bytes);
        attr_set = true;
    }

    vq_zero_kernel<<<1, 1>>>();
    vq_main_kernel<<<GRID, TPB, smem_bytes>>>(z, cb, out);
    vq_finalize_kernel<<<1, 1>>>(out, out_size - 1);
}

// round 5
// speedup vs baseline: 1.2121x; 1.2121x over previous
#include <cuda_runtime.h>
#include <cuda_bf16.h>
#include <cstdint>

// ---------------- problem constants ----------------
#define D_    64
#define HW_   4096
#define K_    512
#define NPTS  131072                    // 32*4096 points
#define NELEM ((long long)NPTS * D_)    // 8388608
#define EPS_SCREEN 4.0e-4f

#define MTPB  256
#define MGRID (NPTS / 128)              // 1024 CTAs, 128 points each

// smem byte offsets
#define SM_Y     0        // 512 f32
#define SM_BKF   2048     // 128 int
#define SM_FLAG  2560     // 128 int
#define SM_RED   3072     // 8 f32
#define SM_AHI   4096     // 128 rows * 128 B (z hi, bf16, SW128)
#define SM_ALO   20480    // 128 rows * 128 B (z residual, bf16, SW128)
#define SM_B     36864    // 512 rows * 128 B (codebook bf16, SW128)
#define SMEM_TOTAL 102400 // 100 KB -> 2 CTAs/SM

// ---------------- device globals ----------------
__device__ double       g_loss_accum;
__device__ int          g_flag_count;
__device__ int          g_worklist[NPTS];
__device__ unsigned int g_cb_bf16[K_ * D_ / 2];  // packed bf16x2, row-major
__device__ float        g_y[K_];                 // exact sequential sum e_i^2

#define SWZ128(off) ((off) ^ (((off) >> 3) & 0x70))

__device__ __forceinline__ void mma_bf16(float* c, const uint32_t* a,
                                         uint32_t b0, uint32_t b1) {
    asm volatile(
        "mma.sync.aligned.m16n8k16.row.col.f32.bf16.bf16.f32 "
        "{%0,%1,%2,%3}, {%4,%5,%6,%7}, {%8,%9}, {%0,%1,%2,%3};"
        : "+f"(c[0]), "+f"(c[1]), "+f"(c[2]), "+f"(c[3])
        : "r"(a[0]), "r"(a[1]), "r"(a[2]), "r"(a[3]), "r"(b0), "r"(b1));
}

__device__ __forceinline__ uint32_t pack_bf16x2(float lo, float hi) {
    uint32_t u;
    asm("cvt.rn.bf16x2.f32 %0, %1, %2;" : "=r"(u) : "f"(hi), "f"(lo));
    return u;
}

// Merge two (min1, argmin, min2) candidate sets; ties -> smaller index.
__device__ __forceinline__ void merge3(float& m1, int& k1, float& m2,
                                       float om1, int ok1, float om2) {
    if (om1 < m1 || (om1 == m1 && ok1 < k1)) {
        m2 = fminf(m1, om2);
        m1 = om1; k1 = ok1;
    } else {
        m2 = fminf(m2, om1);
    }
}

// ---------------- prep: y_k exact, codebook -> bf16, zero scalars ----------------
__global__ void vq_prep_kernel(const float* __restrict__ cb) {
    int k = blockIdx.x * blockDim.x + threadIdx.x;   // 0..511
    if (k == 0) { g_loss_accum = 0.0; g_flag_count = 0; }
    if (k >= K_) return;
    const float* e = cb + k * D_;
    float s = 0.f;
    #pragma unroll
    for (int i = 0; i < D_; i++) s = __fadd_rn(s, __fmul_rn(e[i], e[i]));
    g_y[k] = s;
    #pragma unroll
    for (int j = 0; j < 32; j++)
        g_cb_bf16[k * 32 + j] = pack_bf16x2(e[2 * j], e[2 * j + 1]);
}

// ---------------- main: mma.sync bf16 split screen ----------------
__global__ __launch_bounds__(MTPB, 2)
void vq_main_kernel(const float* __restrict__ z,
                    const float* __restrict__ cb,
                    float* __restrict__ out) {
    extern __shared__ char smem[];
    float* s_y    = (float*)(smem + SM_Y);
    int*   s_bkf  = (int*)(smem + SM_BKF);
    int*   s_flag = (int*)(smem + SM_FLAG);
    float* s_red  = (float*)(smem + SM_RED);

    const int tid  = threadIdx.x;
    const int wid  = tid >> 5;
    const int lane = tid & 31;
    const int p    = tid & 127;     // point within tile (staging/output role)
    const int half = tid >> 7;      // channel half (staging/output role)

    const int base = blockIdx.x * 128;
    const int b    = base >> 12;
    const int hw0  = base & (HW_ - 1);
    const float* zb = z + (size_t)b * D_ * HW_ + hw0;

    // ---- stage A: z -> bf16 hi + bf16 residual, SW128 rows of 128 B ----
    {
        const int c0 = half * 32;
        #pragma unroll
        for (int j = 0; j < 16; j++) {
            int c = c0 + 2 * j;
            float v0 = __ldg(zb + (size_t)c * HW_ + p);
            float v1 = __ldg(zb + (size_t)(c + 1) * HW_ + p);
            float h0 = __bfloat162float(__float2bfloat16(v0));
            float h1 = __bfloat162float(__float2bfloat16(v1));
            uint32_t off = (uint32_t)(p * 128 + c * 2);
            *(uint32_t*)(smem + SM_AHI + SWZ128(off)) = pack_bf16x2(h0, h1);
            *(uint32_t*)(smem + SM_ALO + SWZ128(off)) =
                pack_bf16x2(v0 - h0, v1 - h1);
        }
    }
    // ---- stage B: codebook bf16 rows, SW128 ----
    {
        const uint4* src = (const uint4*)g_cb_bf16;  // 4096 x 16B
        #pragma unroll
        for (int i = tid; i < 4096; i += MTPB) {
            uint32_t off = (uint32_t)(i * 16);
            *(uint4*)(smem + SM_B + SWZ128(off)) = src[i];
        }
        for (int i = tid; i < K_; i += MTPB) s_y[i] = g_y[i];
    }
    __syncthreads();

    // ---- MMA phase: warp w handles points [w*16, w*16+16) ----
    const int g  = lane >> 2;     // groupID (row within m16 halves / B col)
    const int tg = lane & 3;      // thread-in-group (k index)
    const int row0 = wid * 16 + g;

    uint32_t ah[4][4], al[4][4];
    #pragma unroll
    for (int ks = 0; ks < 4; ks++) {
        uint32_t o = (uint32_t)(row0 * 128 + ks * 32 + tg * 4);
        ah[ks][0] = *(uint32_t*)(smem + SM_AHI + SWZ128(o));
        ah[ks][1] = *(uint32_t*)(smem + SM_AHI + SWZ128(o + 8 * 128));
        ah[ks][2] = *(uint32_t*)(smem + SM_AHI + SWZ128(o + 16));
        ah[ks][3] = *(uint32_t*)(smem + SM_AHI + SWZ128(o + 8 * 128 + 16));
        al[ks][0] = *(uint32_t*)(smem + SM_ALO + SWZ128(o));
        al[ks][1] = *(uint32_t*)(smem + SM_ALO + SWZ128(o + 8 * 128));
        al[ks][2] = *(uint32_t*)(smem + SM_ALO + SWZ128(o + 16));
        al[ks][3] = *(uint32_t*)(smem + SM_ALO + SWZ128(o + 8 * 128 + 16));
    }

    float m1a = 3.4e38f, m2a = 3.4e38f; int k1a = K_;
    float m1b = 3.4e38f, m2b = 3.4e38f; int k1b = K_;

    #pragma unroll 4
    for (int nb = 0; nb < 64; nb++) {
        float acc[4] = {0.f, 0.f, 0.f, 0.f};
        const uint32_t brow = (uint32_t)((nb * 8 + g) * 128 + tg * 4);
        #pragma unroll
        for (int ks = 0; ks < 4; ks++) {
            uint32_t bo = brow + ks * 32;
            uint32_t b0 = *(uint32_t*)(smem + SM_B + SWZ128(bo));
            uint32_t b1 = *(uint32_t*)(smem + SM_B + SWZ128(bo + 16));
            mma_bf16(acc, ah[ks], b0, b1);
            mma_bf16(acc, al[ks], b0, b1);
        }
        const int c0 = nb * 8 + tg * 2;
        float2 y2 = *(const float2*)&s_y[c0];
        float t0 = fmaf(-2.f, acc[0], y2.x);
        float t1 = fmaf(-2.f, acc[1], y2.y);
        float t2 = fmaf(-2.f, acc[2], y2.x);
        float t3 = fmaf(-2.f, acc[3], y2.y);
        // row0 (point row0): columns ascending -> strict < keeps first index
        if (t0 < m1a) { m2a = m1a; m1a = t0; k1a = c0; }     else m2a = fminf(m2a, t0);
        if (t1 < m1a) { m2a = m1a; m1a = t1; k1a = c0 + 1; } else m2a = fminf(m2a, t1);
        // row0+8
        if (t2 < m1b) { m2b = m1b; m1b = t2; k1b = c0; }     else m2b = fminf(m2b, t2);
        if (t3 < m1b) { m2b = m1b; m1b = t3; k1b = c0 + 1; } else m2b = fminf(m2b, t3);
    }

    // quad reduce (lanes sharing a row differ only in tg = bits 0..1)
    #pragma unroll
    for (int off = 1; off <= 2; off <<= 1) {
        float om1 = __shfl_xor_sync(0xffffffffu, m1a, off);
        int   ok1 = __shfl_xor_sync(0xffffffffu, k1a, off);
        float om2 = __shfl_xor_sync(0xffffffffu, m2a, off);
        merge3(m1a, k1a, m2a, om1, ok1, om2);
        om1 = __shfl_xor_sync(0xffffffffu, m1b, off);
        ok1 = __shfl_xor_sync(0xffffffffu, k1b, off);
        om2 = __shfl_xor_sync(0xffffffffu, m2b, off);
        merge3(m1b, k1b, m2b, om1, ok1, om2);
    }

    if (tg == 0) {
        int p0 = row0;            // point index within tile
        int f0 = (m2a - m1a) < EPS_SCREEN;
        int f1 = (m2b - m1b) < EPS_SCREEN;
        s_bkf[p0] = k1a;     s_flag[p0] = f0;
        s_bkf[p0 + 8] = k1b; s_flag[p0 + 8] = f1;
        if (f0) { int i = atomicAdd(&g_flag_count, 1); g_worklist[i] = base + p0; }
        if (f1) { int i = atomicAdd(&g_flag_count, 1); g_worklist[i] = base + p0 + 8; }
    }
    __syncthreads();

    // ---- output + loss for clear winners ----
    float lsum = 0.f;
    if (!s_flag[p]) {
        const int bestk = s_bkf[p];
        const float* e = cb + bestk * D_;
        float* op = out + (size_t)b * D_ * HW_ + hw0 + p;
        const int c0 = half * 32;
        #pragma unroll
        for (int j = 0; j < 32; j++) {
            int c = c0 + j;
            float zv = __ldg(zb + (size_t)c * HW_ + p);
            float q  = __ldg(e + c);
            float dd = __fadd_rn(q, -zv);
            lsum = __fmaf_rn(dd, dd, lsum);
            op[(size_t)c * HW_] = __fadd_rn(zv, dd);
        }
    }
    #pragma unroll
    for (int off = 16; off > 0; off >>= 1)
        lsum += __shfl_down_sync(0xffffffffu, lsum, off);
    if (lane == 0) s_red[wid] = lsum;
    __syncthreads();
    if (tid < 32) {
        float v = (tid < 8) ? s_red[tid] : 0.f;
        #pragma unroll
        for (int off = 4; off > 0; off >>= 1)
            v += __shfl_down_sync(0xffffffffu, v, off);
        if (tid == 0) atomicAdd(&g_loss_accum, (double)v);
    }
}

// ---------------- fallback: bit-exact scan, one point per warp ----------------
#define FB_CTAS 128
#define FB_TPB  256
__global__ __launch_bounds__(FB_TPB)
void vq_fallback_kernel(const float* __restrict__ z,
                        const float* __restrict__ cb,
                        float* __restrict__ out) {
    const int lane = threadIdx.x & 31;
    const int gw   = (blockIdx.x * FB_TPB + threadIdx.x) >> 5;
    const int nw   = (FB_CTAS * FB_TPB) >> 5;   // 1024 warps
    const int cnt  = g_flag_count;

    for (int w = gw; w < cnt; w += nw) {
        const int n  = g_worklist[w];
        const int b  = n >> 12;
        const int hw = n & (HW_ - 1);
        const float* zp = z + (size_t)b * D_ * HW_ + hw;

        float zv[D_];
        #pragma unroll
        for (int i = 0; i < D_; i++) zv[i] = __ldg(zp + (size_t)i * HW_);
        float x = 0.f;
        #pragma unroll
        for (int i = 0; i < D_; i++) x = __fadd_rn(x, __fmul_rn(zv[i], zv[i]));

        // lane handles codes [lane*16, lane*16+16), exact reference chain
        float bd = 3.4e38f; int bk = K_;
        #pragma unroll 1
        for (int kk = 0; kk < 16; kk++) {
            const int k = lane * 16 + kk;
            const float4* e4 = (const float4*)(cb + k * D_);
            float m = 0.f;
            #pragma unroll
            for (int i = 0; i < D_ / 4; i++) {
                float4 e = __ldg(e4 + i);
                m = __fmaf_rn(zv[4 * i + 0], e.x, m);
                m = __fmaf_rn(zv[4 * i + 1], e.y, m);
                m = __fmaf_rn(zv[4 * i + 2], e.z, m);
                m = __fmaf_rn(zv[4 * i + 3], e.w, m);
            }
            float d = __fadd_rn(__fadd_rn(x, g_y[k]), -__fmul_rn(2.f, m));
            if (d < bd) { bd = d; bk = k; }
        }
        // lexicographic (d, k) min across lanes => first-index tie rule
        #pragma unroll
        for (int off = 16; off > 0; off >>= 1) {
            float od = __shfl_down_sync(0xffffffffu, bd, off);
            int   ok = __shfl_down_sync(0xffffffffu, bk, off);
            if (od < bd || (od == bd && ok < bk)) { bd = od; bk = ok; }
        }
        bk = __shfl_sync(0xffffffffu, bk, 0);

        float* op = out + (size_t)b * D_ * HW_ + hw;
        const float* e = cb + bk * D_;
        float ls = 0.f;
        #pragma unroll
        for (int h = 0; h < 2; h++) {
            int c = lane + 32 * h;
            float q  = __ldg(e + c);
            float dd = __fadd_rn(q, -zv[c]);
            ls = __fmaf_rn(dd, dd, ls);
            op[(size_t)c * HW_] = __fadd_rn(zv[c], dd);
        }
        #pragma unroll
        for (int off = 16; off > 0; off >>= 1)
            ls += __shfl_down_sync(0xffffffffu, ls, off);
        if (lane == 0) atomicAdd(&g_loss_accum, (double)ls);
    }
}

__global__ void vq_finalize_kernel(float* __restrict__ out, int loss_idx) {
    out[loss_idx] = (float)(g_loss_accum * 1.25 / (double)NELEM);
}

extern "C" void kernel_launch(void* const* d_in, const int* in_sizes, int n_in,
                              void* d_out, int out_size) {
    const float* z  = (const float*)d_in[0];
    const float* cb = (const float*)d_in[1];
    float* out = (float*)d_out;

    static bool attr_set = false;
    if (!attr_set) {
        cudaFuncSetAttribute(vq_main_kernel,
                             cudaFuncAttributeMaxDynamicSharedMemorySize,
                             SMEM_TOTAL);
        attr_set = true;
    }

    vq_prep_kernel<<<2, 256>>>(cb);
    vq_main_kernel<<<MGRID, MTPB, SMEM_TOTAL>>>(z, cb, out);
    vq_fallback_kernel<<<FB_CTAS, FB_TPB>>>(z, cb, out);
    vq_finalize_kernel<<<1, 1>>>(out, out_size - 1);
}

// round 6
// speedup vs baseline: 2.0720x; 1.7094x over previous
#include <cuda_runtime.h>
#include <cuda_bf16.h>
#include <cstdint>

// ---------------- problem constants ----------------
#define D_    64
#define HW_   4096
#define K_    512
#define NPTS  131072
#define NELEM 8388608LL

// Provable candidate window: ulp(x+y) <= 2*ulp(128)=3.05e-5 for x<256,
// + 2*eps_screen (3-pass bf16 split, eps<~3e-6) -> 4.1e-5 with margin.
#define W0 4.1e-5f

#define MTPB   256
#define MGRID  148
#define NTILES (NPTS / 128)   // 1024

// ---- smem byte offsets (A/B tiles 1024-aligned for SW128) ----
#define SM_Y     0        // 512 f32 (exact sequential sum e^2)
#define SM_BKF   2048     // 128 int
#define SM_FLAG  2560     // 128 int
#define SM_RED   3072     // 8 f32
#define SM_Z     3136     // 128 * 65 f32 (padded, conflict-free)
#define SM_AHI   36864    // 128 rows * 128 B  bf16 z-hi  (SW128)
#define SM_ALO   53248    // 128 rows * 128 B  bf16 z-lo  (SW128)
#define SM_BH    69632    // 512 rows * 128 B  bf16 cb-hi (SW128)
#define SM_BL    135168   // 512 rows * 128 B  bf16 cb-lo (SW128)
#define SMEM_TOTAL 200704 // ~196 KB -> 1 CTA/SM

// ---------------- device globals (zero-init; finalize resets) ----------------
__device__ double g_loss_accum;
__device__ int    g_flag_count;
__device__ int    g_worklist[NPTS];
__device__ float  g_y[K_];

#define SWZ128(off) ((off) ^ (((off) >> 3) & 0x70))

__device__ __forceinline__ void mma_bf16(float* c, const uint32_t* a,
                                         uint32_t b0, uint32_t b1) {
    asm volatile(
        "mma.sync.aligned.m16n8k16.row.col.f32.bf16.bf16.f32 "
        "{%0,%1,%2,%3}, {%4,%5,%6,%7}, {%8,%9}, {%0,%1,%2,%3};"
        : "+f"(c[0]), "+f"(c[1]), "+f"(c[2]), "+f"(c[3])
        : "r"(a[0]), "r"(a[1]), "r"(a[2]), "r"(a[3]), "r"(b0), "r"(b1));
}
__device__ __forceinline__ uint32_t pack_bf16x2(float lo, float hi) {
    uint32_t u;
    asm("cvt.rn.bf16x2.f32 %0, %1, %2;" : "=r"(u) : "f"(hi), "f"(lo));
    return u;
}

// Insert t (key ascending stream) into sorted top-4; strict < keeps
// earlier (smaller) index first on value ties.
__device__ __forceinline__ void ins4(float t, int kt,
        float& m0, float& m1, float& m2, float& m3,
        int& k0, int& k1, int& k2, int& k3) {
    if (t < m3) {
        m3 = t; k3 = kt;
        if (m3 < m2) { float f=m2; m2=m3; m3=f; int q=k2; k2=k3; k3=q; }
        if (m2 < m1) { float f=m1; m1=m2; m2=f; int q=k1; k1=k2; k2=q; }
        if (m1 < m0) { float f=m0; m0=m1; m1=f; int q=k0; k0=k1; k1=q; }
    }
}
// Lexicographic (value, index) compare-exchange.
__device__ __forceinline__ void ce(float& ma, int& ka, float& mb, int& kb) {
    if (mb < ma || (mb == ma && kb < ka)) {
        float f = ma; ma = mb; mb = f;
        int q = ka; ka = kb; kb = q;
    }
}
// Merge own sorted top-4 with xor-neighbor's -> global sorted top-4.
__device__ __forceinline__ void merge_xor(int off,
        float& m0, float& m1, float& m2, float& m3,
        int& k0, int& k1, int& k2, int& k3) {
    float n0 = __shfl_xor_sync(0xffffffffu, m0, off);
    float n1 = __shfl_xor_sync(0xffffffffu, m1, off);
    float n2 = __shfl_xor_sync(0xffffffffu, m2, off);
    float n3 = __shfl_xor_sync(0xffffffffu, m3, off);
    int   q0 = __shfl_xor_sync(0xffffffffu, k0, off);
    int   q1 = __shfl_xor_sync(0xffffffffu, k1, off);
    int   q2 = __shfl_xor_sync(0xffffffffu, k2, off);
    int   q3 = __shfl_xor_sync(0xffffffffu, k3, off);
    // bitonic lower-half of two ascending 4-lists
    ce(m0, k0, n3, q3); ce(m1, k1, n2, q2);
    ce(m2, k2, n1, q1); ce(m3, k3, n0, q0);
    // sort the 4 survivors
    ce(m0, k0, m2, k2); ce(m1, k1, m3, k3);
    ce(m0, k0, m1, k1); ce(m2, k2, m3, k3);
    ce(m1, k1, m2, k2);
}

// Exact reference distance: d = fl( fl(x + y_k) - 2*m ), m = sequential fma chain.
__device__ __forceinline__ float exact_d(const float* __restrict__ cb, int k,
                                         const float* s_zrow, float x, float yk) {
    const float4* e4 = (const float4*)(cb + k * D_);
    float m = 0.f;
    #pragma unroll
    for (int i = 0; i < 16; i++) {
        float4 e = __ldg(e4 + i);
        m = __fmaf_rn(s_zrow[4*i+0], e.x, m);
        m = __fmaf_rn(s_zrow[4*i+1], e.y, m);
        m = __fmaf_rn(s_zrow[4*i+2], e.z, m);
        m = __fmaf_rn(s_zrow[4*i+3], e.w, m);
    }
    return __fadd_rn(__fadd_rn(x, yk), -__fmul_rn(2.f, m));
}

// ---------------- main: persistent, bf16 3-pass split screen ----------------
__global__ __launch_bounds__(MTPB, 1)
void vq_main_kernel(const float* __restrict__ z,
                    const float* __restrict__ cb,
                    float* __restrict__ out) {
    extern __shared__ char smem[];
    float* s_y    = (float*)(smem + SM_Y);
    int*   s_bkf  = (int*)(smem + SM_BKF);
    int*   s_flag = (int*)(smem + SM_FLAG);
    float* s_red  = (float*)(smem + SM_RED);
    float* s_z    = (float*)(smem + SM_Z);     // [128][65]

    const int tid  = threadIdx.x;
    const int wid  = tid >> 5;
    const int lane = tid & 31;
    const int g    = lane >> 2;
    const int tg   = lane & 3;
    const int p    = tid & 127;
    const int half = tid >> 7;

    // ---- stage B once: fp32 -> bf16 hi/lo SW128, exact y ----
    for (int k = tid; k < K_; k += MTPB) {
        const float4* e4 = (const float4*)(cb + k * D_);
        float ev[D_];
        #pragma unroll
        for (int i = 0; i < 16; i++) {
            float4 v = __ldg(e4 + i);
            ev[4*i] = v.x; ev[4*i+1] = v.y; ev[4*i+2] = v.z; ev[4*i+3] = v.w;
        }
        float s = 0.f;
        #pragma unroll
        for (int i = 0; i < D_; i++) s = __fadd_rn(s, __fmul_rn(ev[i], ev[i]));
        s_y[k] = s;
        if (blockIdx.x == 0) g_y[k] = s;
        #pragma unroll
        for (int j = 0; j < 32; j++) {
            float v0 = ev[2*j], v1 = ev[2*j+1];
            float h0 = __bfloat162float(__float2bfloat16(v0));
            float h1 = __bfloat162float(__float2bfloat16(v1));
            uint32_t off = (uint32_t)(k * 128 + j * 4);
            *(uint32_t*)(smem + SM_BH + SWZ128(off)) = pack_bf16x2(h0, h1);
            *(uint32_t*)(smem + SM_BL + SWZ128(off)) = pack_bf16x2(v0 - h0, v1 - h1);
        }
    }
    __syncthreads();

    for (int tile = blockIdx.x; tile < NTILES; tile += gridDim.x) {
        const int base = tile * 128;
        const int b    = base >> 12;
        const int hw0  = base & (HW_ - 1);
        const float* zb = z + (size_t)b * D_ * HW_ + hw0;

        // ---- stage A: z fp32 -> smem (padded) + bf16 hi/lo SW128 ----
        {
            const int c0 = half * 32;
            #pragma unroll
            for (int j = 0; j < 16; j++) {
                int c = c0 + 2 * j;
                float v0 = __ldg(zb + (size_t)c * HW_ + p);
                float v1 = __ldg(zb + (size_t)(c + 1) * HW_ + p);
                s_z[p * 65 + c]     = v0;
                s_z[p * 65 + c + 1] = v1;
                float h0 = __bfloat162float(__float2bfloat16(v0));
                float h1 = __bfloat162float(__float2bfloat16(v1));
                uint32_t off = (uint32_t)(p * 128 + c * 2);
                *(uint32_t*)(smem + SM_AHI + SWZ128(off)) = pack_bf16x2(h0, h1);
                *(uint32_t*)(smem + SM_ALO + SWZ128(off)) = pack_bf16x2(v0 - h0, v1 - h1);
            }
        }
        __syncthreads();

        // ---- A fragments (layout identical to validated R5) ----
        const int row0 = wid * 16 + g;
        uint32_t ah[4][4], al[4][4];
        #pragma unroll
        for (int ks = 0; ks < 4; ks++) {
            uint32_t o = (uint32_t)(row0 * 128 + ks * 32 + tg * 4);
            ah[ks][0] = *(uint32_t*)(smem + SM_AHI + SWZ128(o));
            ah[ks][1] = *(uint32_t*)(smem + SM_AHI + SWZ128(o + 8 * 128));
            ah[ks][2] = *(uint32_t*)(smem + SM_AHI + SWZ128(o + 16));
            ah[ks][3] = *(uint32_t*)(smem + SM_AHI + SWZ128(o + 8 * 128 + 16));
            al[ks][0] = *(uint32_t*)(smem + SM_ALO + SWZ128(o));
            al[ks][1] = *(uint32_t*)(smem + SM_ALO + SWZ128(o + 8 * 128));
            al[ks][2] = *(uint32_t*)(smem + SM_ALO + SWZ128(o + 16));
            al[ks][3] = *(uint32_t*)(smem + SM_ALO + SWZ128(o + 8 * 128 + 16));
        }

        // ---- nb loop: 3-pass MMA + top-4 tracking (rows a,b) ----
        float a0 = 3.4e38f, a1 = 3.4e38f, a2 = 3.4e38f, a3 = 3.4e38f;
        float b0 = 3.4e38f, b1 = 3.4e38f, b2 = 3.4e38f, b3 = 3.4e38f;
        int   ja0 = K_, ja1 = K_, ja2 = K_, ja3 = K_;
        int   jb0 = K_, jb1 = K_, jb2 = K_, jb3 = K_;

        #pragma unroll 2
        for (int nb = 0; nb < 64; nb++) {
            float acc[4] = {0.f, 0.f, 0.f, 0.f};
            const uint32_t brow = (uint32_t)((nb * 8 + g) * 128 + tg * 4);
            #pragma unroll
            for (int ks = 0; ks < 4; ks++) {
                uint32_t bo = brow + ks * 32;
                uint32_t bh0 = *(uint32_t*)(smem + SM_BH + SWZ128(bo));
                uint32_t bh1 = *(uint32_t*)(smem + SM_BH + SWZ128(bo + 16));
                mma_bf16(acc, ah[ks], bh0, bh1);
                mma_bf16(acc, al[ks], bh0, bh1);
                uint32_t bl0 = *(uint32_t*)(smem + SM_BL + SWZ128(bo));
                uint32_t bl1 = *(uint32_t*)(smem + SM_BL + SWZ128(bo + 16));
                mma_bf16(acc, ah[ks], bl0, bl1);
            }
            const int c0 = nb * 8 + tg * 2;
            float2 y2 = *(const float2*)&s_y[c0];
            float t0 = fmaf(-2.f, acc[0], y2.x);
            float t1 = fmaf(-2.f, acc[1], y2.y);
            float t2 = fmaf(-2.f, acc[2], y2.x);
            float t3 = fmaf(-2.f, acc[3], y2.y);
            ins4(t0, c0,     a0, a1, a2, a3, ja0, ja1, ja2, ja3);
            ins4(t1, c0 + 1, a0, a1, a2, a3, ja0, ja1, ja2, ja3);
            ins4(t2, c0,     b0, b1, b2, b3, jb0, jb1, jb2, jb3);
            ins4(t3, c0 + 1, b0, b1, b2, b3, jb0, jb1, jb2, jb3);
        }

        // ---- quad merge -> global top-4 per point ----
        merge_xor(1, a0, a1, a2, a3, ja0, ja1, ja2, ja3);
        merge_xor(2, a0, a1, a2, a3, ja0, ja1, ja2, ja3);
        merge_xor(1, b0, b1, b2, b3, jb0, jb1, jb2, jb3);
        merge_xor(2, b0, b1, b2, b3, jb0, jb1, jb2, jb3);

        // ---- decision + inline exact check (tg==0 owns rows row0, row0+8) ----
        if (tg == 0) {
            #pragma unroll
            for (int r = 0; r < 2; r++) {
                const int   pp = row0 + r * 8;
                const float m0 = r ? b0 : a0, m1 = r ? b1 : a1;
                const float m2 = r ? b2 : a2, m3 = r ? b3 : a3;
                const int   q0 = r ? jb0 : ja0, q1 = r ? jb1 : ja1;
                const int   q2 = r ? jb2 : ja2;
                if (m1 > m0 + W0) {
                    s_bkf[pp] = q0; s_flag[pp] = 0;
                } else if (m3 <= m0 + W0) {
                    s_bkf[pp] = 0; s_flag[pp] = 1;   // rare: 4+ candidates
                    int i = atomicAdd(&g_flag_count, 1);
                    g_worklist[i] = base + pp;
                } else {
                    const float* zr = &s_z[pp * 65];
                    float x = 0.f;
                    #pragma unroll
                    for (int i = 0; i < D_; i++)
                        x = __fadd_rn(x, __fmul_rn(zr[i], zr[i]));
                    float d0 = exact_d(cb, q0, zr, x, s_y[q0]);
                    float d1 = exact_d(cb, q1, zr, x, s_y[q1]);
                    float db; int kb;
                    if (d0 < d1 || (d0 == d1 && q0 < q1)) { db = d0; kb = q0; }
                    else                                   { db = d1; kb = q1; }
                    if (m2 <= m0 + W0) {
                        float d2 = exact_d(cb, q2, zr, x, s_y[q2]);
                        if (d2 < db || (d2 == db && q2 < kb)) { kb = q2; }
                    }
                    s_bkf[pp] = kb; s_flag[pp] = 0;
                }
            }
        }
        __syncthreads();

        // ---- output + loss (z from smem, codebook rows via LDG.128) ----
        float lsum = 0.f;
        if (!s_flag[p]) {
            const int bestk = s_bkf[p];
            const float4* e4 = (const float4*)(cb + bestk * D_);
            float* op = out + (size_t)b * D_ * HW_ + hw0 + p;
            const int c0 = half * 32;
            #pragma unroll
            for (int j4 = 0; j4 < 8; j4++) {
                float4 e = __ldg(e4 + c0 / 4 + j4);
                #pragma unroll
                for (int u = 0; u < 4; u++) {
                    int c = c0 + 4 * j4 + u;
                    float q = (u == 0) ? e.x : (u == 1) ? e.y : (u == 2) ? e.z : e.w;
                    float zv = s_z[p * 65 + c];
                    float dd = __fadd_rn(q, -zv);
                    lsum = __fmaf_rn(dd, dd, lsum);
                    op[(size_t)c * HW_] = __fadd_rn(zv, dd);
                }
            }
        }
        #pragma unroll
        for (int off = 16; off > 0; off >>= 1)
            lsum += __shfl_down_sync(0xffffffffu, lsum, off);
        if (lane == 0) s_red[wid] = lsum;
        __syncthreads();
        if (tid == 0) {
            float v = 0.f;
            #pragma unroll
            for (int i = 0; i < 8; i++) v += s_red[i];
            atomicAdd(&g_loss_accum, (double)v);
        }
        __syncthreads();   // protect s_z / A tiles before next stage
    }
}

// ---------------- fallback: bit-exact full scan, one point per warp ----------------
#define FB_CTAS 64
#define FB_TPB  256
__global__ __launch_bounds__(FB_TPB)
void vq_fallback_kernel(const float* __restrict__ z,
                        const float* __restrict__ cb,
                        float* __restrict__ out) {
    const int lane = threadIdx.x & 31;
    const int gw   = (blockIdx.x * FB_TPB + threadIdx.x) >> 5;
    const int nw   = (FB_CTAS * FB_TPB) >> 5;
    const int cnt  = g_flag_count;

    for (int w = gw; w < cnt; w += nw) {
        const int n  = g_worklist[w];
        const int b  = n >> 12;
        const int hw = n & (HW_ - 1);
        const float* zp = z + (size_t)b * D_ * HW_ + hw;

        float zv[D_];
        #pragma unroll
        for (int i = 0; i < D_; i++) zv[i] = __ldg(zp + (size_t)i * HW_);
        float x = 0.f;
        #pragma unroll
        for (int i = 0; i < D_; i++) x = __fadd_rn(x, __fmul_rn(zv[i], zv[i]));

        float bd = 3.4e38f; int bk = K_;
        #pragma unroll 1
        for (int kk = 0; kk < 16; kk++) {
            const int k = lane * 16 + kk;
            const float4* e4 = (const float4*)(cb + k * D_);
            float m = 0.f;
            #pragma unroll
            for (int i = 0; i < 16; i++) {
                float4 e = __ldg(e4 + i);
                m = __fmaf_rn(zv[4*i+0], e.x, m);
                m = __fmaf_rn(zv[4*i+1], e.y, m);
                m = __fmaf_rn(zv[4*i+2], e.z, m);
                m = __fmaf_rn(zv[4*i+3], e.w, m);
            }
            float d = __fadd_rn(__fadd_rn(x, g_y[k]), -__fmul_rn(2.f, m));
            if (d < bd) { bd = d; bk = k; }
        }
        #pragma unroll
        for (int off = 16; off > 0; off >>= 1) {
            float od = __shfl_down_sync(0xffffffffu, bd, off);
            int   ok = __shfl_down_sync(0xffffffffu, bk, off);
            if (od < bd || (od == bd && ok < bk)) { bd = od; bk = ok; }
        }
        bk = __shfl_sync(0xffffffffu, bk, 0);

        float* op = out + (size_t)b * D_ * HW_ + hw;
        const float* e = cb + bk * D_;
        float ls = 0.f;
        #pragma unroll
        for (int h = 0; h < 2; h++) {
            int c = lane + 32 * h;
            float q  = __ldg(e + c);
            float dd = __fadd_rn(q, -zv[c]);
            ls = __fmaf_rn(dd, dd, ls);
            op[(size_t)c * HW_] = __fadd_rn(zv[c], dd);
        }
        #pragma unroll
        for (int off = 16; off > 0; off >>= 1)
            ls += __shfl_down_sync(0xffffffffu, ls, off);
        if (lane == 0) atomicAdd(&g_loss_accum, (double)ls);
    }
}

// ---------------- finalize: write loss, reset state for graph replays ----------------
__global__ void vq_finalize_kernel(float* __restrict__ out, int loss_idx) {
    out[loss_idx] = (float)(g_loss_accum * 1.25 / (double)NELEM);
    g_loss_accum = 0.0;
    g_flag_count = 0;
}

extern "C" void kernel_launch(void* const* d_in, const int* in_sizes, int n_in,
                              void* d_out, int out_size) {
    const float* z  = (const float*)d_in[0];
    const float* cb = (const float*)d_in[1];
    float* out = (float*)d_out;

    static bool attr_set = false;
    if (!attr_set) {
        cudaFuncSetAttribute(vq_main_kernel,
                             cudaFuncAttributeMaxDynamicSharedMemorySize,
                             SMEM_TOTAL);
        attr_set = true;
    }

    vq_main_kernel<<<MGRID, MTPB, SMEM_TOTAL>>>(z, cb, out);
    vq_fallback_kernel<<<FB_CTAS, FB_TPB>>>(z, cb, out);
    vq_finalize_kernel<<<1, 1>>>(out, out_size - 1);
}

// round 7
// speedup vs baseline: 2.9413x; 1.4195x over previous
#include <cuda_runtime.h>
#include <cuda_bf16.h>
#include <cstdint>

// ---------------- problem constants ----------------
#define D_    64
#define HW_   4096
#define K_    512
#define NPTS  131072
#define NELEM 8388608LL

// Provable candidate window: ulp(x+y) <= 2*ulp(128)=3.05e-5 for x<256,
// + 2*eps_screen (3-pass bf16 split) -> 4.1e-5 with margin. (Validated R6.)
#define W0 4.1e-5f

#define MTPB   512
#define MGRID  148
#define NTILES (NPTS / 128)   // 1024

// ---- smem byte offsets (A/B tiles 1024-aligned for SW128) ----
#define SM_Y     0        // 512 f32
#define SM_BKF   2048     // 128 int
#define SM_FLAG  2560     // 128 int
#define SM_RED   3072     // 16 f32
#define SM_M1    3136     // 128*2 f32
#define SM_M2    4160     // 128*2 f32
#define SM_K1    5184     // 128*2 int
#define SM_Z     6208     // 128*65 f32 (padded rows)
#define SM_AHI   39936    // 128 rows * 128 B  bf16 z-hi  (SW128)
#define SM_ALO   56320    // 128 rows * 128 B  bf16 z-lo  (SW128)
#define SM_BH    72704    // 512 rows * 128 B  bf16 cb-hi (SW128)
#define SM_BL    138240   // 512 rows * 128 B  bf16 cb-lo (SW128)
#define SMEM_TOTAL 203776 // ~199 KB -> 1 CTA/SM

// ---------------- device globals (zero-init; finalize resets) ----------------
__device__ double g_loss_accum;
__device__ int    g_flag_count;
__device__ int    g_worklist[NPTS];
__device__ float  g_y[K_];

#define SWZ128(off) ((off) ^ (((off) >> 3) & 0x70))

__device__ __forceinline__ uint32_t smem_u32_of(const void* p) {
    uint32_t a;
    asm("{ .reg .u64 t; cvta.to.shared.u64 t, %1; cvt.u32.u64 %0, t; }"
        : "=r"(a) : "l"(p));
    return a;
}
__device__ __forceinline__ void mma_bf16(float* c, const uint32_t* a,
                                         uint32_t b0, uint32_t b1) {
    asm volatile(
        "mma.sync.aligned.m16n8k16.row.col.f32.bf16.bf16.f32 "
        "{%0,%1,%2,%3}, {%4,%5,%6,%7}, {%8,%9}, {%0,%1,%2,%3};"
        : "+f"(c[0]), "+f"(c[1]), "+f"(c[2]), "+f"(c[3])
        : "r"(a[0]), "r"(a[1]), "r"(a[2]), "r"(a[3]), "r"(b0), "r"(b1));
}
__device__ __forceinline__ void ldsm_x4(uint32_t* r, uint32_t addr) {
    asm volatile(
        "ldmatrix.sync.aligned.m8n8.x4.shared.b16 {%0,%1,%2,%3}, [%4];"
        : "=r"(r[0]), "=r"(r[1]), "=r"(r[2]), "=r"(r[3]) : "r"(addr));
}
__device__ __forceinline__ uint32_t pack_bf16x2(float lo, float hi) {
    uint32_t u;
    asm("cvt.rn.bf16x2.f32 %0, %1, %2;" : "=r"(u) : "f"(hi), "f"(lo));
    return u;
}
// Merge candidate sets {(m1,k1), m2} U {(om1,ok1), om2}; ties -> smaller index.
__device__ __forceinline__ void merge3(float& m1, int& k1, float& m2,
                                       float om1, int ok1, float om2) {
    if (om1 < m1 || (om1 == m1 && ok1 < k1)) {
        m2 = fminf(m1, om2);
        m1 = om1; k1 = ok1;
    } else {
        m2 = fminf(m2, om1);
    }
}

// ---------------- main: persistent, bf16 3-pass split screen ----------------
__global__ __launch_bounds__(MTPB, 1)
void vq_main_kernel(const float* __restrict__ z,
                    const float* __restrict__ cb,
                    float* __restrict__ out) {
    extern __shared__ char smem[];
    const uint32_t smb = smem_u32_of(smem);
    float* s_y    = (float*)(smem + SM_Y);
    int*   s_bkf  = (int*)(smem + SM_BKF);
    int*   s_flag = (int*)(smem + SM_FLAG);
    float* s_red  = (float*)(smem + SM_RED);
    float* s_m1   = (float*)(smem + SM_M1);
    float* s_m2   = (float*)(smem + SM_M2);
    int*   s_k1   = (int*)(smem + SM_K1);
    float* s_z    = (float*)(smem + SM_Z);     // [128][65]

    const int tid  = threadIdx.x;
    const int wid  = tid >> 5;
    const int lane = tid & 31;
    const int g    = lane >> 2;
    const int tg   = lane & 3;
    const int p    = tid & 127;   // staging/output point
    const int q4   = tid >> 7;    // staging/output channel quarter (0..3)

    // ---- stage B once: one code per thread ----
    {
        const int k = tid;        // 0..511
        const float4* e4 = (const float4*)(cb + k * D_);
        float ev[D_];
        #pragma unroll
        for (int i = 0; i < 16; i++) {
            float4 v = __ldg(e4 + i);
            ev[4*i] = v.x; ev[4*i+1] = v.y; ev[4*i+2] = v.z; ev[4*i+3] = v.w;
        }
        float s = 0.f;
        #pragma unroll
        for (int i = 0; i < D_; i++) s = __fadd_rn(s, __fmul_rn(ev[i], ev[i]));
        s_y[k] = s;
        if (blockIdx.x == 0) g_y[k] = s;
        #pragma unroll
        for (int j = 0; j < 32; j++) {
            float v0 = ev[2*j], v1 = ev[2*j+1];
            float h0 = __bfloat162float(__float2bfloat16(v0));
            float h1 = __bfloat162float(__float2bfloat16(v1));
            uint32_t off = (uint32_t)(k * 128 + j * 4);
            *(uint32_t*)(smem + SM_BH + SWZ128(off)) = pack_bf16x2(h0, h1);
            *(uint32_t*)(smem + SM_BL + SWZ128(off)) = pack_bf16x2(v0 - h0, v1 - h1);
        }
    }
    __syncthreads();

    // warp roles: point rows (wid>>1)*16 + g / +8 ; code half nh
    const int row0 = (wid >> 1) * 16 + g;
    const int nh   = wid & 1;

    // ldmatrix lane addresses (per-thread constant column part)
    const int lr = lane & 7;         // row within 8-row block
    const int ms = lane >> 3;        // matrix select 0..3
    const uint32_t colx0 = (uint32_t)((ms * 16) ^ (lr << 4));        // k-bytes 0..63
    const uint32_t colx1 = (uint32_t)((64 + ms * 16) ^ (lr << 4));   // k-bytes 64..127
    const uint32_t browz = (uint32_t)((nh * 256 + lr) * 128);

    for (int tile = blockIdx.x; tile < NTILES; tile += gridDim.x) {
        const int base = tile * 128;
        const int b    = base >> 12;
        const int hw0  = base & (HW_ - 1);
        const float* zb = z + (size_t)b * D_ * HW_ + hw0;

        // ---- stage A: z fp32 -> smem (padded) + bf16 hi/lo SW128 ----
        {
            const int c0s = q4 * 16;
            #pragma unroll
            for (int j = 0; j < 8; j++) {
                int c = c0s + 2 * j;
                float v0 = __ldg(zb + (size_t)c * HW_ + p);
                float v1 = __ldg(zb + (size_t)(c + 1) * HW_ + p);
                s_z[p * 65 + c]     = v0;
                s_z[p * 65 + c + 1] = v1;
                float h0 = __bfloat162float(__float2bfloat16(v0));
                float h1 = __bfloat162float(__float2bfloat16(v1));
                uint32_t off = (uint32_t)(p * 128 + c * 2);
                *(uint32_t*)(smem + SM_AHI + SWZ128(off)) = pack_bf16x2(h0, h1);
                *(uint32_t*)(smem + SM_ALO + SWZ128(off)) = pack_bf16x2(v0 - h0, v1 - h1);
            }
        }
        __syncthreads();

        // ---- A fragments (validated layout) ----
        uint32_t ah[4][4], al[4][4];
        #pragma unroll
        for (int ks = 0; ks < 4; ks++) {
            uint32_t o = (uint32_t)(row0 * 128 + ks * 32 + tg * 4);
            ah[ks][0] = *(uint32_t*)(smem + SM_AHI + SWZ128(o));
            ah[ks][1] = *(uint32_t*)(smem + SM_AHI + SWZ128(o + 8 * 128));
            ah[ks][2] = *(uint32_t*)(smem + SM_AHI + SWZ128(o + 16));
            ah[ks][3] = *(uint32_t*)(smem + SM_AHI + SWZ128(o + 8 * 128 + 16));
            al[ks][0] = *(uint32_t*)(smem + SM_ALO + SWZ128(o));
            al[ks][1] = *(uint32_t*)(smem + SM_ALO + SWZ128(o + 8 * 128));
            al[ks][2] = *(uint32_t*)(smem + SM_ALO + SWZ128(o + 16));
            al[ks][3] = *(uint32_t*)(smem + SM_ALO + SWZ128(o + 8 * 128 + 16));
        }

        uint32_t bh0 = smb + SM_BH + browz + colx0;
        uint32_t bh1 = smb + SM_BH + browz + colx1;
        uint32_t bl0 = smb + SM_BL + browz + colx0;
        uint32_t bl1 = smb + SM_BL + browz + colx1;

        float m1a = 3.4e38f, m2a = 3.4e38f;
        float m1b = 3.4e38f, m2b = 3.4e38f;
        int   k1a = K_, k1b = K_;

        #pragma unroll 4
        for (int nb = 0; nb < 32; nb++) {
            uint32_t h1[4], h2[4], lo1[4], lo2[4];
            ldsm_x4(h1,  bh0); ldsm_x4(h2,  bh1);
            ldsm_x4(lo1, bl0); ldsm_x4(lo2, bl1);
            bh0 += 1024; bh1 += 1024; bl0 += 1024; bl1 += 1024;

            float acc[4] = {0.f, 0.f, 0.f, 0.f};
            mma_bf16(acc, ah[0], h1[0], h1[1]);
            mma_bf16(acc, al[0], h1[0], h1[1]);
            mma_bf16(acc, ah[0], lo1[0], lo1[1]);
            mma_bf16(acc, ah[1], h1[2], h1[3]);
            mma_bf16(acc, al[1], h1[2], h1[3]);
            mma_bf16(acc, ah[1], lo1[2], lo1[3]);
            mma_bf16(acc, ah[2], h2[0], h2[1]);
            mma_bf16(acc, al[2], h2[0], h2[1]);
            mma_bf16(acc, ah[2], lo2[0], lo2[1]);
            mma_bf16(acc, ah[3], h2[2], h2[3]);
            mma_bf16(acc, al[3], h2[2], h2[3]);
            mma_bf16(acc, ah[3], lo2[2], lo2[3]);

            const int c0 = nh * 256 + nb * 8 + tg * 2;
            float2 y2 = *(const float2*)&s_y[c0];
            float t0 = fmaf(-2.f, acc[0], y2.x);
            float t1 = fmaf(-2.f, acc[1], y2.y);
            float t2 = fmaf(-2.f, acc[2], y2.x);
            float t3 = fmaf(-2.f, acc[3], y2.y);
            if (t0 < m1a) { m2a = m1a; m1a = t0; k1a = c0; }     else m2a = fminf(m2a, t0);
            if (t1 < m1a) { m2a = m1a; m1a = t1; k1a = c0 + 1; } else m2a = fminf(m2a, t1);
            if (t2 < m1b) { m2b = m1b; m1b = t2; k1b = c0; }     else m2b = fminf(m2b, t2);
            if (t3 < m1b) { m2b = m1b; m1b = t3; k1b = c0 + 1; } else m2b = fminf(m2b, t3);
        }

        // quad merge (tg bits)
        #pragma unroll
        for (int off = 1; off <= 2; off <<= 1) {
            float om1 = __shfl_xor_sync(0xffffffffu, m1a, off);
            int   ok1 = __shfl_xor_sync(0xffffffffu, k1a, off);
            float om2 = __shfl_xor_sync(0xffffffffu, m2a, off);
            merge3(m1a, k1a, m2a, om1, ok1, om2);
            om1 = __shfl_xor_sync(0xffffffffu, m1b, off);
            ok1 = __shfl_xor_sync(0xffffffffu, k1b, off);
            om2 = __shfl_xor_sync(0xffffffffu, m2b, off);
            merge3(m1b, k1b, m2b, om1, ok1, om2);
        }
        if (tg == 0) {
            s_m1[row0 * 2 + nh] = m1a; s_m2[row0 * 2 + nh] = m2a;
            s_k1[row0 * 2 + nh] = k1a;
            s_m1[(row0 + 8) * 2 + nh] = m1b; s_m2[(row0 + 8) * 2 + nh] = m2b;
            s_k1[(row0 + 8) * 2 + nh] = k1b;
        }
        __syncthreads();

        // ---- decision: merge halves, window -> worklist ----
        if (tid < 128) {
            float m1 = s_m1[tid * 2], m2v = s_m2[tid * 2];
            int   k1 = s_k1[tid * 2];
            merge3(m1, k1, m2v, s_m1[tid*2+1], s_k1[tid*2+1], s_m2[tid*2+1]);
            int fl = (m2v - m1) < W0;
            s_bkf[tid] = k1; s_flag[tid] = fl;
            if (fl) {
                int i = atomicAdd(&g_flag_count, 1);
                g_worklist[i] = base + tid;
            }
        }
        __syncthreads();

        // ---- output + loss (z from smem, codebook via LDG.128) ----
        float lsum = 0.f;
        if (!s_flag[p]) {
            const int bestk = s_bkf[p];
            const float4* e4 = (const float4*)(cb + bestk * D_);
            float* op = out + (size_t)b * D_ * HW_ + hw0 + p;
            #pragma unroll
            for (int j4 = 0; j4 < 4; j4++) {
                float4 e = __ldg(e4 + q4 * 4 + j4);
                #pragma unroll
                for (int u = 0; u < 4; u++) {
                    int c = q4 * 16 + 4 * j4 + u;
                    float qq = (u == 0) ? e.x : (u == 1) ? e.y : (u == 2) ? e.z : e.w;
                    float zv = s_z[p * 65 + c];
                    float dd = __fadd_rn(qq, -zv);
                    lsum = __fmaf_rn(dd, dd, lsum);
                    op[(size_t)c * HW_] = __fadd_rn(zv, dd);
                }
            }
        }
        #pragma unroll
        for (int off = 16; off > 0; off >>= 1)
            lsum += __shfl_down_sync(0xffffffffu, lsum, off);
        if (lane == 0) s_red[wid] = lsum;
        __syncthreads();
        if (tid == 0) {
            float v = 0.f;
            #pragma unroll
            for (int i = 0; i < 16; i++) v += s_red[i];
            atomicAdd(&g_loss_accum, (double)v);
        }
        __syncthreads();   // protect smem tiles before next tile's staging
    }
}

// ---------------- fallback: bit-exact full scan, one point per warp ----------------
#define FB_CTAS 64
#define FB_TPB  256
__global__ __launch_bounds__(FB_TPB)
void vq_fallback_kernel(const float* __restrict__ z,
                        const float* __restrict__ cb,
                        float* __restrict__ out) {
    const int lane = threadIdx.x & 31;
    const int gw   = (blockIdx.x * FB_TPB + threadIdx.x) >> 5;
    const int nw   = (FB_CTAS * FB_TPB) >> 5;
    const int cnt  = g_flag_count;

    for (int w = gw; w < cnt; w += nw) {
        const int n  = g_worklist[w];
        const int b  = n >> 12;
        const int hw = n & (HW_ - 1);
        const float* zp = z + (size_t)b * D_ * HW_ + hw;

        float zv[D_];
        #pragma unroll
        for (int i = 0; i < D_; i++) zv[i] = __ldg(zp + (size_t)i * HW_);
        float x = 0.f;
        #pragma unroll
        for (int i = 0; i < D_; i++) x = __fadd_rn(x, __fmul_rn(zv[i], zv[i]));

        float bd = 3.4e38f; int bk = K_;
        #pragma unroll 1
        for (int kk = 0; kk < 16; kk++) {
            const int k = lane * 16 + kk;
            const float4* e4 = (const float4*)(cb + k * D_);
            float m = 0.f;
            #pragma unroll
            for (int i = 0; i < 16; i++) {
                float4 e = __ldg(e4 + i);
                m = __fmaf_rn(zv[4*i+0], e.x, m);
                m = __fmaf_rn(zv[4*i+1], e.y, m);
                m = __fmaf_rn(zv[4*i+2], e.z, m);
                m = __fmaf_rn(zv[4*i+3], e.w, m);
            }
            float d = __fadd_rn(__fadd_rn(x, g_y[k]), -__fmul_rn(2.f, m));
            if (d < bd) { bd = d; bk = k; }
        }
        #pragma unroll
        for (int off = 16; off > 0; off >>= 1) {
            float od = __shfl_down_sync(0xffffffffu, bd, off);
            int   ok = __shfl_down_sync(0xffffffffu, bk, off);
            if (od < bd || (od == bd && ok < bk)) { bd = od; bk = ok; }
        }
        bk = __shfl_sync(0xffffffffu, bk, 0);

        float* op = out + (size_t)b * D_ * HW_ + hw;
        const float* e = cb + bk * D_;
        float ls = 0.f;
        #pragma unroll
        for (int h = 0; h < 2; h++) {
            int c = lane + 32 * h;
            float qq = __ldg(e + c);
            float dd = __fadd_rn(qq, -zv[c]);
            ls = __fmaf_rn(dd, dd, ls);
            op[(size_t)c * HW_] = __fadd_rn(zv[c], dd);
        }
        #pragma unroll
        for (int off = 16; off > 0; off >>= 1)
            ls += __shfl_down_sync(0xffffffffu, ls, off);
        if (lane == 0) atomicAdd(&g_loss_accum, (double)ls);
    }
}

// ---------------- finalize: write loss, reset state for graph replays ----------------
__global__ void vq_finalize_kernel(float* __restrict__ out, int loss_idx) {
    out[loss_idx] = (float)(g_loss_accum * 1.25 / (double)NELEM);
    g_loss_accum = 0.0;
    g_flag_count = 0;
}

extern "C" void kernel_launch(void* const* d_in, const int* in_sizes, int n_in,
                              void* d_out, int out_size) {
    const float* z  = (const float*)d_in[0];
    const float* cb = (const float*)d_in[1];
    float* out = (float*)d_out;

    static bool attr_set = false;
    if (!attr_set) {
        cudaFuncSetAttribute(vq_main_kernel,
                             cudaFuncAttributeMaxDynamicSharedMemorySize,
                             SMEM_TOTAL);
        attr_set = true;
    }

    vq_main_kernel<<<MGRID, MTPB, SMEM_TOTAL>>>(z, cb, out);
    vq_fallback_kernel<<<FB_CTAS, FB_TPB>>>(z, cb, out);
    vq_finalize_kernel<<<1, 1>>>(out, out_size - 1);
}